// round 5
// baseline (speedup 1.0000x reference)
#include <cuda_runtime.h>
#include <math.h>

typedef unsigned long long ull;
typedef unsigned int u32;

#define B_   64
#define H_   1024
#define I_   512
#define L_   4
#define S_   512
#define H4   4096
#define KT   32
#define NCTA 128     // 4 layers * 32 CTAs
#define NTHR 256

// Hidden state double-buffered by wave parity: [parity][layer][row*H + col]
__device__ float g_h[2][L_][B_ * H_];
__device__ unsigned g_bar_count;
__device__ volatile unsigned g_bar_gen;

__device__ __forceinline__ ull bcast2(float v) {
    ull r; asm("mov.b64 %0, {%1, %1};" : "=l"(r) : "f"(v)); return r;
}
__device__ __forceinline__ void fma2(ull& d, ull a, ull b) {
    asm("fma.rn.f32x2 %0, %1, %2, %0;" : "+l"(d) : "l"(a), "l"(b));
}
__device__ __forceinline__ float2 u2f(ull v) {
    float2 f; asm("mov.b64 {%0, %1}, %2;" : "=f"(f.x), "=f"(f.y) : "l"(v)); return f;
}
__device__ __forceinline__ u32 sm_u32(const void* p) {
    u32 a;
    asm("{.reg .u64 t; cvta.to.shared.u64 t, %1; cvt.u32.u64 %0, t;}" : "=r"(a) : "l"(p));
    return a;
}

__device__ __forceinline__ void grid_sync() {
    __syncthreads();
    if (threadIdx.x == 0) {
        __threadfence();
        unsigned gen = g_bar_gen;
        if (atomicAdd(&g_bar_count, 1u) == NCTA - 1u) {
            g_bar_count = 0;
            __threadfence();
            g_bar_gen = gen + 1u;
        } else {
            while (g_bar_gen == gen) __nanosleep(64);
        }
        __threadfence();
    }
    __syncthreads();
}

// Issue cp.async for one weight tile: 32 k-rows x 128 z-cols (4 gates x 32 hcols)
// into smem layout [kk][lane] = float4{g0,g1,g2,g3}. 16 x 4B cp.async per thread.
__device__ __forceinline__ void issue_w(const float* __restrict__ Wk0, int hc0,
                                        u32 dst, int lane, int r) {
    #pragma unroll
    for (int j = 0; j < 4; j++) {
        const int kk = r + 8 * j;
        const float* s = Wk0 + (size_t)kk * H4 + hc0 + lane;
        const u32 d = dst + (u32)((kk * 32 + lane) * 16);
        #pragma unroll
        for (int g = 0; g < 4; g++)
            asm volatile("cp.async.ca.shared.global [%0], [%1], 4;"
                         :: "r"(d + 4u * g), "l"(s + 1024 * g));
    }
}

// Register prefetch of one input tile: thread owns k-col (k0+lane), rows r*8..r*8+7.
__device__ __forceinline__ void ldg_inp(const float* __restrict__ inp, int ldi, int k0,
                                        int lane, int r, float pa[8]) {
    #pragma unroll
    for (int j = 0; j < 8; j++)
        pa[j] = __ldcg(inp + (size_t)(r * 8 + j) * ldi + k0 + lane);
}

// Conflict-free staging: 2x STS.128 per thread. smem row index = lane (= k within
// tile), 16 groups of 4 rows, group position XOR-swizzled by (lane & 15).
__device__ __forceinline__ void sts_inp(float* __restrict__ buf, int lane, int r,
                                        const float pa[8]) {
    float4* p0 = reinterpret_cast<float4*>(buf + lane * 64 + (((2 * r)     ^ (lane & 15)) << 2));
    float4* p1 = reinterpret_cast<float4*>(buf + lane * 64 + (((2 * r + 1) ^ (lane & 15)) << 2));
    *p0 = make_float4(pa[0], pa[1], pa[2], pa[3]);
    *p1 = make_float4(pa[4], pa[5], pa[6], pa[7]);
}

__global__ void __launch_bounds__(NTHR, 1)
lstm_persist(const float* __restrict__ x,
             const float* __restrict__ Wx0, const float* __restrict__ Wh0,
             const float* __restrict__ b0,
             const float* __restrict__ Wxr, const float* __restrict__ Whr,
             const float* __restrict__ br,
             float* __restrict__ out)
{
    __shared__ __align__(16) float4 w_s[2][KT * 32];   // 32 KB
    __shared__ __align__(16) float  inp_s[2][KT * 64]; // 16 KB

    const int layer = blockIdx.x >> 5;
    const int hc0   = (blockIdx.x & 31) * 32;
    const int t     = threadIdx.x;
    const int lane  = t & 31;
    const int r     = t >> 5;
    const int r2    = 2 * r;
    const int hcol  = hc0 + lane;

    const float* WA   = (layer == 0) ? Wx0 : Wxr + (size_t)(layer - 1) * H_ * H4;
    const float* WB   = (layer == 0) ? Wh0 : Whr + (size_t)(layer - 1) * H_ * H4;
    const float* bias = (layer == 0) ? b0  : br + (size_t)(layer - 1) * H4;
    const int    KA   = (layer == 0) ? I_  : H_;
    const int    ntA  = KA / KT;
    const int    nt   = ntA + H_ / KT;

    const u32 wsm0 = sm_u32(&w_s[0][0]);
    const u32 wsm1 = sm_u32(&w_s[1][0]);

    float b4[4];
    #pragma unroll
    for (int g = 0; g < 4; g++)
        b4[g] = __ldg(bias + g * 1024 + hcol);

    float creg[8];
    #pragma unroll
    for (int i = 0; i < 8; i++) creg[i] = 0.f;

    const size_t HS = (size_t)S_ * B_ * H_;
    const size_t BH = (size_t)B_ * H_;

    for (int w = 0; w < S_ + L_ - 1; w++) {
        const int s = w - layer;
        if (s >= 0 && s < S_) {
            const int prPrev = (w & 1) ^ 1;
            const int prCur  = w & 1;

            const float* inA = (layer == 0) ? (x + (size_t)s * B_ * I_)
                                            : &g_h[prPrev][layer - 1][0];
            const int    ldA = (layer == 0) ? I_ : H_;
            const float* inB = &g_h[prPrev][layer][0];

            ull acc[4][4];
            #pragma unroll
            for (int p = 0; p < 4; p++)
                #pragma unroll
                for (int g = 0; g < 4; g++)
                    acc[p][g] = bcast2(b4[g]);

            // ---- fused GEMM over inA (ntA tiles) then inB (32 tiles) ----
            float pa[8];
            issue_w(WA, hc0, wsm0, lane, r);
            asm volatile("cp.async.commit_group;" ::: "memory");
            ldg_inp(inA, ldA, 0, lane, r, pa);
            sts_inp(&inp_s[0][0], lane, r, pa);
            asm volatile("cp.async.wait_group 0;" ::: "memory");
            __syncthreads();

            for (int tt = 0; tt < nt; tt++) {
                const int cur = tt & 1;
                const bool more = (tt + 1 < nt);
                if (more) {
                    const float* Wn; const float* ipn; int ldn, kn;
                    if (tt + 1 < ntA) {
                        Wn = WA + (size_t)(tt + 1) * KT * H4;
                        ipn = inA; ldn = ldA; kn = (tt + 1) * KT;
                    } else {
                        const int u = tt + 1 - ntA;
                        Wn = WB + (size_t)u * KT * H4;
                        ipn = inB; ldn = H_; kn = u * KT;
                    }
                    issue_w(Wn, hc0, cur ? wsm0 : wsm1, lane, r);
                    asm volatile("cp.async.commit_group;" ::: "memory");
                    ldg_inp(ipn, ldn, kn, lane, r, pa);
                }

                const float4* wp = &w_s[cur][lane];
                const float*  ib = &inp_s[cur][0];
                #pragma unroll
                for (int kk = 0; kk < KT; kk++) {
                    const float4 wv = wp[kk * 32];
                    const ull w0 = bcast2(wv.x), w1 = bcast2(wv.y);
                    const ull w2 = bcast2(wv.z), w3 = bcast2(wv.w);
                    const float* base = ib + kk * 64;
                    const ulonglong2 A0 = *reinterpret_cast<const ulonglong2*>(
                        base + ((r2 ^ (kk & 15)) << 2));
                    const ulonglong2 A1 = *reinterpret_cast<const ulonglong2*>(
                        base + (((r2 + 1) ^ (kk & 15)) << 2));
                    fma2(acc[0][0], A0.x, w0); fma2(acc[0][1], A0.x, w1);
                    fma2(acc[0][2], A0.x, w2); fma2(acc[0][3], A0.x, w3);
                    fma2(acc[1][0], A0.y, w0); fma2(acc[1][1], A0.y, w1);
                    fma2(acc[1][2], A0.y, w2); fma2(acc[1][3], A0.y, w3);
                    fma2(acc[2][0], A1.x, w0); fma2(acc[2][1], A1.x, w1);
                    fma2(acc[2][2], A1.x, w2); fma2(acc[2][3], A1.x, w3);
                    fma2(acc[3][0], A1.y, w0); fma2(acc[3][1], A1.y, w1);
                    fma2(acc[3][2], A1.y, w2); fma2(acc[3][3], A1.y, w3);
                }

                if (more) sts_inp(&inp_s[cur ^ 1][0], lane, r, pa);
                asm volatile("cp.async.wait_group 0;" ::: "memory");
                __syncthreads();
            }

            // ---- activations + state update ----
            float* hw = &g_h[prCur][layer][0];
            #pragma unroll
            for (int p = 0; p < 4; p++) {
                float2 zi = u2f(acc[p][0]);
                float2 zf = u2f(acc[p][1]);
                float2 zg = u2f(acc[p][2]);
                float2 zo = u2f(acc[p][3]);
                #pragma unroll
                for (int half = 0; half < 2; half++) {
                    const float vi = half ? zi.y : zi.x;
                    const float vf = half ? zf.y : zf.x;
                    const float vg = half ? zg.y : zg.x;
                    const float vo = half ? zo.y : zo.x;
                    const int rr  = p * 2 + half;
                    const int row = r * 8 + rr;
                    const float ig = 1.f / (1.f + expf(-vi));
                    const float fg = 1.f / (1.f + expf(-vf));
                    const float og = 1.f / (1.f + expf(-vo));
                    const float cn = fg * creg[rr] + ig * tanhf(vg);
                    const float hn = og * tanhf(cn);
                    creg[rr] = cn;
                    hw[row * H_ + hcol] = hn;
                    if (layer == L_ - 1)
                        out[(size_t)s * BH + row * H_ + hcol] = hn;
                    if (s == S_ - 1) {
                        out[HS + (size_t)layer * BH + row * H_ + hcol] = hn;
                        out[HS + (size_t)L_ * BH + (size_t)layer * BH + row * H_ + hcol] = cn;
                    }
                }
            }
        }
        if (w < S_ + L_ - 2) grid_sync();
    }
}

extern "C" void kernel_launch(void* const* d_in, const int* in_sizes, int n_in,
                              void* d_out, int out_size)
{
    const float* x   = (const float*)d_in[0];   // [512, 64, 512]
    const float* Wx0 = (const float*)d_in[1];   // [512, 4096]
    const float* Wh0 = (const float*)d_in[2];   // [1024, 4096]
    const float* b0  = (const float*)d_in[3];   // [4096]
    const float* Wxr = (const float*)d_in[4];   // [3, 1024, 4096]
    const float* Whr = (const float*)d_in[5];   // [3, 1024, 4096]
    const float* br  = (const float*)d_in[6];   // [3, 4096]
    float* out = (float*)d_out;

    void* hp;
    cudaGetSymbolAddress(&hp, g_h);
    cudaMemsetAsync(hp, 0, sizeof(float) * 2 * L_ * B_ * H_, 0);

    lstm_persist<<<NCTA, NTHR>>>(x, Wx0, Wh0, b0, Wxr, Whr, br, out);
}

// round 7
// speedup vs baseline: 1.4867x; 1.4867x over previous
#include <cuda_runtime.h>
#include <cuda_bf16.h>
#include <math.h>
#include <cstdint>

typedef unsigned int u32;
typedef unsigned long long ull;

#define NCTA 128
#define NTHR 256
#define HS_  33554432ull      // 512*64*1024
#define BH_  65536

// Weight images in B-fragment order: 15360 chunks x 2048 u32 (126 MB)
__device__ __align__(16) u32 g_W[31457280];
// x images in A-fragment order: (s*32+c) * 1024 u32 (64 MB)
__device__ __align__(16) u32 g_x[16777216];
// h images in A-fragment order: [parity][layer][64 chunks * 1024 u32]
__device__ __align__(16) u32 g_hA[2][4][65536];
__device__ unsigned g_bar_count;
__device__ volatile unsigned g_bar_gen;

__device__ __forceinline__ u32 sm_u32(const void* p) {
    u32 a;
    asm("{.reg .u64 t; cvta.to.shared.u64 t, %1; cvt.u32.u64 %0, t;}" : "=r"(a) : "l"(p));
    return a;
}
__device__ __forceinline__ void cpa16(u32 dst, const void* src) {
    asm volatile("cp.async.cg.shared.global [%0], [%1], 16;" :: "r"(dst), "l"(src));
}
#define CPA_COMMIT() asm volatile("cp.async.commit_group;" ::: "memory")
#define CPA_WAIT1()  asm volatile("cp.async.wait_group 1;" ::: "memory")
#define CPA_WAIT0()  asm volatile("cp.async.wait_group 0;" ::: "memory")

__device__ __forceinline__ void mma16816(float* c, const u32* a, const u32* b) {
    asm("mma.sync.aligned.m16n8k16.row.col.f32.bf16.bf16.f32 "
        "{%0,%1,%2,%3}, {%4,%5,%6,%7}, {%8,%9}, {%0,%1,%2,%3};"
        : "+f"(c[0]), "+f"(c[1]), "+f"(c[2]), "+f"(c[3])
        : "r"(a[0]), "r"(a[1]), "r"(a[2]), "r"(a[3]), "r"(b[0]), "r"(b[1]));
}

__device__ __forceinline__ u32 pack2(float v0, float v1, bool lo) {
    __nv_bfloat16 h0 = __float2bfloat16(v0), h1 = __float2bfloat16(v1);
    if (lo) {
        h0 = __float2bfloat16(v0 - __bfloat162float(h0));
        h1 = __float2bfloat16(v1 - __bfloat162float(h1));
    }
    u32 u0 = ((__nv_bfloat16_raw)h0).x, u1 = ((__nv_bfloat16_raw)h1).x;
    return u0 | (u1 << 16);
}

__device__ __forceinline__ void grid_sync() {
    __syncthreads();
    if (threadIdx.x == 0) {
        __threadfence();
        unsigned gen = g_bar_gen;
        if (atomicAdd(&g_bar_count, 1u) == NCTA - 1u) {
            g_bar_count = 0;
            __threadfence();
            g_bar_gen = gen + 1u;
        } else {
            while (g_bar_gen == gen) __nanosleep(64);
        }
        __threadfence();
    }
    __syncthreads();
}

// Pack x into A-fragment order. Chunk layout: [mt 0..3][hi/lo][128 words],
// word = lane*4+reg; reg0:(row=gid,k=tig*2), reg1:(row+8), reg2:(k+8), reg3:(row+8,k+8)
__global__ void __launch_bounds__(256) prep_x(const float* __restrict__ x)
{
    const int s = blockIdx.x >> 5, c = blockIdx.x & 31;
    const int t = threadIdx.x;
    u32* dst = g_x + (size_t)blockIdx.x * 1024;
    #pragma unroll
    for (int q = 0; q < 4; q++) {
        const int gw = t + 256 * q;
        const int mt = gw >> 8, rem = gw & 255, hl = rem >> 7, w = rem & 127;
        const int lane = w >> 2, reg = w & 3;
        const int row = mt * 16 + (lane >> 2) + (reg & 1) * 8;
        const int k   = c * 16 + (lane & 3) * 2 + (reg >> 1) * 8;
        const float* p = x + (size_t)s * 32768 + row * 512 + k;
        dst[gw] = pack2(p[0], p[1], hl != 0);
    }
}

// Pack weights into B-fragment order. Chunk layout: [nt 0..15][hi/lo][64 words],
// word = lane*2+reg; reg0:(k=tig*2,n=gid), reg1:(k+8). n = jloc*4 + gate.
__global__ void __launch_bounds__(256) prep_w(
    const float* __restrict__ Wx0, const float* __restrict__ Wh0,
    const float* __restrict__ Wxr, const float* __restrict__ Whr)
{
    const int b = blockIdx.x;
    int l, nblk, c;
    if (b < 3072) { l = 0; nblk = b / 96; c = b % 96; }
    else { int r = b - 3072; l = 1 + r / 4096; r %= 4096; nblk = r / 128; c = r % 128; }
    const int ntA = (l == 0) ? 32 : 64;
    const float* Wsrc; int kb;
    if (c < ntA) { Wsrc = (l == 0) ? Wx0 : Wxr + (size_t)(l - 1) * 4194304; kb = c * 16; }
    else         { Wsrc = (l == 0) ? Wh0 : Whr + (size_t)(l - 1) * 4194304; kb = (c - ntA) * 16; }
    u32* dst = g_W + (size_t)b * 2048;
    const int t = threadIdx.x;
    #pragma unroll
    for (int q = 0; q < 8; q++) {
        const int gw = t + 256 * q;
        const int nt = gw >> 7, rem = gw & 127, hl = rem >> 6, w = rem & 63;
        const int lane = w >> 1, reg = w & 1;
        const int n = nt * 8 + (lane >> 2);
        const int zc = (n & 3) * 1024 + nblk * 32 + (n >> 2);
        const int k = kb + (lane & 3) * 2 + reg * 8;
        dst[gw] = pack2(Wsrc[(size_t)k * 4096 + zc], Wsrc[(size_t)(k + 1) * 4096 + zc], hl != 0);
    }
}

// Persistent wavefront LSTM. Stage = A(4KB) + W(8KB); double buffered; zbuf 32KB.
#define SMEM_DYN 57344

__global__ void __launch_bounds__(NTHR, 1)
lstm_persist(const float* __restrict__ b0, const float* __restrict__ br,
             float* __restrict__ out)
{
    extern __shared__ u32 sm[];
    u32* stg[2] = { sm, sm + 3072 };
    float* zbuf = (float*)(sm + 6144);
    const u32 smb[2] = { sm_u32(stg[0]), sm_u32(stg[1]) };

    const int layer = blockIdx.x >> 5, nblk = blockIdx.x & 31;
    const int t = threadIdx.x, lane = t & 31, wid = t >> 5;
    const int mt = wid & 3, nh = wid >> 2;
    const int gid = lane >> 2, tig = lane & 3;
    const int hcol = nblk * 32 + lane;
    const int ntA = (layer == 0) ? 32 : 64;
    const int nc  = ntA + 64;
    const size_t wbase = (layer == 0) ? (size_t)nblk * 96
                                      : 3072 + ((size_t)(layer - 1) * 32 + nblk) * 128;
    const float* bias = (layer == 0) ? b0 : br + (size_t)(layer - 1) * 4096;

    float b4[4];
    #pragma unroll
    for (int g = 0; g < 4; g++) b4[g] = __ldg(bias + g * 1024 + hcol);
    float creg[8];
    #pragma unroll
    for (int i = 0; i < 8; i++) creg[i] = 0.f;

    // h-image write constants (k dim of next gemm = hcol)
    const int kchunk = hcol >> 4, kl = hcol & 15;
    const int tigk = (kl >> 1) & 3, regk = kl >> 3, byk = kl & 1;

    for (int w = 0; w < 512 + 3; w++) {
        const int s = w - layer;
        if (s >= 0 && s < 512) {
            const int prPrev = (w & 1) ^ 1, prCur = w & 1;

            auto asrc = [&](int c) -> const u32* {
                if (c < ntA)
                    return (layer == 0) ? g_x + ((size_t)s * 32 + c) * 1024
                                        : &g_hA[prPrev][layer - 1][c * 1024];
                return &g_hA[prPrev][layer][(c - ntA) * 1024];
            };
            auto fill = [&](int st, int c) {
                const u32* A = asrc(c);
                const u32* W = g_W + (wbase + c) * 2048;
                const u32 d = smb[st];
                cpa16(d + t * 16u, A + t * 4);
                cpa16(d + 4096u + t * 16u, W + t * 4);
                cpa16(d + 8192u + t * 16u, W + 1024 + t * 4);
                CPA_COMMIT();
            };

            float acc[8][4];
            #pragma unroll
            for (int tt = 0; tt < 8; tt++)
                #pragma unroll
                for (int r = 0; r < 4; r++) acc[tt][r] = 0.f;

            fill(0, 0);
            for (int c = 0; c < nc; c++) {
                const int st = c & 1;
                if (c + 1 < nc) { fill(st ^ 1, c + 1); CPA_WAIT1(); }
                else           { CPA_WAIT0(); }
                __syncthreads();
                const u32* A = stg[st];
                const u32* W = stg[st] + 1024;
                u32 ah[4], al[4];
                *(uint4*)ah = *(const uint4*)&A[(mt * 2 + 0) * 128 + lane * 4];
                *(uint4*)al = *(const uint4*)&A[(mt * 2 + 1) * 128 + lane * 4];
                #pragma unroll
                for (int tt = 0; tt < 8; tt++) {
                    const int nt = nh * 8 + tt;
                    u32 bh[2], bl[2];
                    *(ull*)bh = *(const ull*)&W[(nt * 2 + 0) * 64 + lane * 2];
                    *(ull*)bl = *(const ull*)&W[(nt * 2 + 1) * 64 + lane * 2];
                    mma16816(acc[tt], ah, bh);
                    mma16816(acc[tt], ah, bl);
                    mma16816(acc[tt], al, bh);
                }
                __syncthreads();
            }

            // z -> zbuf[row 0..63][n 0..127]
            const int m0 = mt * 16;
            #pragma unroll
            for (int tt = 0; tt < 8; tt++) {
                const int nb = nh * 64 + tt * 8 + tig * 2;
                *(float2*)&zbuf[(m0 + gid) * 128 + nb]     = make_float2(acc[tt][0], acc[tt][1]);
                *(float2*)&zbuf[(m0 + gid + 8) * 128 + nb] = make_float2(acc[tt][2], acc[tt][3]);
            }
            __syncthreads();

            // cell update: thread owns rows wid*8..+7, hcol = nblk*32+lane
            u32* himg = &g_hA[prCur][layer][0];
            #pragma unroll
            for (int i = 0; i < 8; i++) {
                const int r = wid * 8 + i;
                const float4 z = *(const float4*)&zbuf[r * 128 + lane * 4];
                const float zi = z.x + b4[0], zf = z.y + b4[1];
                const float zg = z.z + b4[2], zo = z.w + b4[3];
                const float ig = 1.f / (1.f + expf(-zi));
                const float fg = 1.f / (1.f + expf(-zf));
                const float og = 1.f / (1.f + expf(-zo));
                const float cn = fg * creg[i] + ig * tanhf(zg);
                const float hn = og * tanhf(cn);
                creg[i] = cn;
                const int rl = r & 15, mtr = r >> 4;
                const int word = ((rl & 7) * 4 + tigk) * 4 + ((rl >> 3) | (regk << 1));
                const u32 ihi = kchunk * 1024 + (mtr * 2 + 0) * 128 + word;
                const u32 ilo = kchunk * 1024 + (mtr * 2 + 1) * 128 + word;
                const __nv_bfloat16 hh = __float2bfloat16(hn);
                const __nv_bfloat16 hl = __float2bfloat16(hn - __bfloat162float(hh));
                ((__nv_bfloat16*)&himg[ihi])[byk] = hh;
                ((__nv_bfloat16*)&himg[ilo])[byk] = hl;
                if (layer == 3) out[(size_t)s * BH_ + r * 1024 + hcol] = hn;
                if (s == 511) {
                    out[HS_ + (size_t)layer * BH_ + r * 1024 + hcol] = hn;
                    out[HS_ + 262144ull + (size_t)layer * BH_ + r * 1024 + hcol] = cn;
                }
            }
        }
        if (w < 512 + 2) grid_sync();
    }
}

extern "C" void kernel_launch(void* const* d_in, const int* in_sizes, int n_in,
                              void* d_out, int out_size)
{
    const float* x   = (const float*)d_in[0];
    const float* Wx0 = (const float*)d_in[1];
    const float* Wh0 = (const float*)d_in[2];
    const float* b0  = (const float*)d_in[3];
    const float* Wxr = (const float*)d_in[4];
    const float* Whr = (const float*)d_in[5];
    const float* br  = (const float*)d_in[6];
    float* out = (float*)d_out;

    void* hp;
    cudaGetSymbolAddress(&hp, g_hA);
    cudaMemsetAsync(hp, 0, sizeof(u32) * 2 * 4 * 65536, 0);

    prep_w<<<15360, 256>>>(Wx0, Wh0, Wxr, Whr);
    prep_x<<<16384, 256>>>(x);

    cudaFuncSetAttribute(lstm_persist, cudaFuncAttributeMaxDynamicSharedMemorySize, SMEM_DYN);
    lstm_persist<<<NCTA, NTHR, SMEM_DYN>>>(b0, br, out);
}

// round 8
// speedup vs baseline: 1.8977x; 1.2764x over previous
#include <cuda_runtime.h>
#include <cuda_bf16.h>
#include <math.h>
#include <cstdint>

typedef unsigned int u32;
typedef unsigned long long ull;

#define NCTA 128
#define NTHR 256
#define HS_  33554432ull
#define BH_  65536
#define SMEM_DYN 81984   // 4*12KB stages + 32KB zbuf + barriers

__device__ __align__(16) u32 g_W[31457280];      // weight images, B-fragment order
__device__ __align__(16) u32 g_x[16777216];      // x images, A-fragment order
__device__ __align__(16) u32 g_hA[2][4][65536];  // h images [parity][layer]
__device__ unsigned g_bar_count;
__device__ volatile unsigned g_bar_gen;

__device__ __forceinline__ u32 sm_u32(const void* p) {
    u32 a;
    asm("{.reg .u64 t; cvta.to.shared.u64 t, %1; cvt.u32.u64 %0, t;}" : "=r"(a) : "l"(p));
    return a;
}
__device__ __forceinline__ void bulk_cp(u32 dst, const void* src, u32 bytes, u32 mbar) {
    asm volatile("cp.async.bulk.shared::cluster.global.mbarrier::complete_tx::bytes "
                 "[%0], [%1], %2, [%3];" :: "r"(dst), "l"(src), "r"(bytes), "r"(mbar) : "memory");
}
__device__ __forceinline__ void mbar_init(u32 a, u32 c) {
    asm volatile("mbarrier.init.shared.b64 [%0], %1;" :: "r"(a), "r"(c) : "memory");
}
__device__ __forceinline__ void mbar_expect(u32 a, u32 tx) {
    asm volatile("mbarrier.arrive.expect_tx.shared.b64 _, [%0], %1;" :: "r"(a), "r"(tx) : "memory");
}
__device__ __forceinline__ void mbar_arrive(u32 a) {
    asm volatile("mbarrier.arrive.shared.b64 _, [%0];" :: "r"(a) : "memory");
}
__device__ __forceinline__ void mbar_wait(u32 a, u32 ph) {
    u32 done = 0;
    while (!done)
        asm volatile("{.reg .pred p; mbarrier.try_wait.parity.acquire.cta.shared::cta.b64 "
                     "p, [%1], %2, 0x989680; selp.b32 %0,1,0,p;}"
                     : "=r"(done) : "r"(a), "r"(ph) : "memory");
}
__device__ __forceinline__ void mma16816(float* c, const u32* a, const u32* b) {
    asm("mma.sync.aligned.m16n8k16.row.col.f32.bf16.bf16.f32 "
        "{%0,%1,%2,%3}, {%4,%5,%6,%7}, {%8,%9}, {%0,%1,%2,%3};"
        : "+f"(c[0]), "+f"(c[1]), "+f"(c[2]), "+f"(c[3])
        : "r"(a[0]), "r"(a[1]), "r"(a[2]), "r"(a[3]), "r"(b[0]), "r"(b[1]));
}
__device__ __forceinline__ u32 pack2(float v0, float v1, bool lo) {
    __nv_bfloat16 h0 = __float2bfloat16(v0), h1 = __float2bfloat16(v1);
    if (lo) {
        h0 = __float2bfloat16(v0 - __bfloat162float(h0));
        h1 = __float2bfloat16(v1 - __bfloat162float(h1));
    }
    u32 u0 = ((__nv_bfloat16_raw)h0).x, u1 = ((__nv_bfloat16_raw)h1).x;
    return u0 | (u1 << 16);
}
__device__ __forceinline__ void grid_sync() {
    __syncthreads();
    if (threadIdx.x == 0) {
        __threadfence();
        asm volatile("fence.proxy.async;" ::: "memory");
        unsigned gen = g_bar_gen;
        if (atomicAdd(&g_bar_count, 1u) == NCTA - 1u) {
            g_bar_count = 0;
            __threadfence();
            g_bar_gen = gen + 1u;
        } else {
            while (g_bar_gen == gen) __nanosleep(64);
        }
        __threadfence();
    }
    __syncthreads();
}

__global__ void __launch_bounds__(256) prep_x(const float* __restrict__ x)
{
    const int s = blockIdx.x >> 5, c = blockIdx.x & 31;
    const int t = threadIdx.x;
    u32* dst = g_x + (size_t)blockIdx.x * 1024;
    #pragma unroll
    for (int q = 0; q < 4; q++) {
        const int gw = t + 256 * q;
        const int mt = gw >> 8, rem = gw & 255, hl = rem >> 7, w = rem & 127;
        const int lane = w >> 2, reg = w & 3;
        const int row = mt * 16 + (lane >> 2) + (reg & 1) * 8;
        const int k   = c * 16 + (lane & 3) * 2 + (reg >> 1) * 8;
        const float* p = x + (size_t)s * 32768 + row * 512 + k;
        dst[gw] = pack2(p[0], p[1], hl != 0);
    }
}

__global__ void __launch_bounds__(256) prep_w(
    const float* __restrict__ Wx0, const float* __restrict__ Wh0,
    const float* __restrict__ Wxr, const float* __restrict__ Whr)
{
    const int b = blockIdx.x;
    int l, nblk, c;
    if (b < 3072) { l = 0; nblk = b / 96; c = b % 96; }
    else { int r = b - 3072; l = 1 + r / 4096; r %= 4096; nblk = r / 128; c = r % 128; }
    const int ntA = (l == 0) ? 32 : 64;
    const float* Wsrc; int kb;
    if (c < ntA) { Wsrc = (l == 0) ? Wx0 : Wxr + (size_t)(l - 1) * 4194304; kb = c * 16; }
    else         { Wsrc = (l == 0) ? Wh0 : Whr + (size_t)(l - 1) * 4194304; kb = (c - ntA) * 16; }
    u32* dst = g_W + (size_t)b * 2048;
    const int t = threadIdx.x;
    #pragma unroll
    for (int q = 0; q < 8; q++) {
        const int gw = t + 256 * q;
        const int nt = gw >> 7, rem = gw & 127, hl = rem >> 6, w = rem & 63;
        const int lane = w >> 1, reg = w & 1;
        const int n = nt * 8 + (lane >> 2);
        const int zc = (n & 3) * 1024 + nblk * 32 + (n >> 2);
        const int k = kb + (lane & 3) * 2 + reg * 8;
        dst[gw] = pack2(Wsrc[(size_t)k * 4096 + zc], Wsrc[(size_t)(k + 1) * 4096 + zc], hl != 0);
    }
}

__global__ void __launch_bounds__(NTHR, 1)
lstm_persist(const float* __restrict__ b0, const float* __restrict__ br,
             float* __restrict__ out)
{
    extern __shared__ __align__(16) u32 sm[];
    float* zbuf = (float*)(sm + 12288);
    const u32 smb = sm_u32(sm);
    const u32 mbF = smb + 81920u;   // full[4], 8B each
    const u32 mbE = smb + 81952u;   // empty[4]

    const int layer = blockIdx.x >> 5, nblk = blockIdx.x & 31;
    const int t = threadIdx.x, lane = t & 31, wid = t >> 5;
    const int mt = wid & 3, nh = wid >> 2;
    const int gid = lane >> 2, tig = lane & 3;
    const int hcol = nblk * 32 + lane;
    const int ntA = (layer == 0) ? 32 : 64;
    const int nc  = ntA + 64;
    const size_t wbase = (layer == 0) ? (size_t)nblk * 96
                                      : 3072 + ((size_t)(layer - 1) * 32 + nblk) * 128;
    const float* bias = (layer == 0) ? b0 : br + (size_t)(layer - 1) * 4096;

    if (t == 0) {
        #pragma unroll
        for (int i = 0; i < 4; i++) { mbar_init(mbF + 8 * i, 1); mbar_init(mbE + 8 * i, 8); }
        asm volatile("fence.proxy.async;" ::: "memory");
    }
    __syncthreads();

    float b4[4];
    #pragma unroll
    for (int g = 0; g < 4; g++) b4[g] = __ldg(bias + g * 1024 + hcol);
    float creg[8];
    #pragma unroll
    for (int i = 0; i < 8; i++) creg[i] = 0.f;

    const int kchunk = hcol >> 4, kl = hcol & 15;
    const int tigk = (kl >> 1) & 3, regk = kl >> 3, byk = kl & 1;

    int gcBase = 0;   // cumulative chunk counter (nc % 4 == 0 always)

    for (int w = 0; w < 512 + 3; w++) {
        const int s = w - layer;
        if (s >= 0 && s < 512) {
            const int prPrev = (w & 1) ^ 1, prCur = w & 1;

            auto asrc = [&](int c) -> const u32* {
                if (c < ntA)
                    return (layer == 0) ? g_x + ((size_t)s * 32 + c) * 1024
                                        : &g_hA[prPrev][layer - 1][c * 1024];
                return &g_hA[prPrev][layer][(c - ntA) * 1024];
            };
            // producer: fill cumulative chunk F (local chunk F - gcBase)
            auto fillF = [&](int F) {
                const int st = F & 3, nf = F >> 2;
                if (nf > 0) mbar_wait(mbE + 8 * st, (u32)(nf - 1) & 1u);
                const u32 full = mbF + 8 * st;
                mbar_expect(full, 12288u);
                const int cl = F - gcBase;
                const u32 d = smb + (u32)st * 12288u;
                bulk_cp(d, asrc(cl), 4096u, full);
                bulk_cp(d + 4096u, g_W + (wbase + cl) * 2048, 8192u, full);
            };

            float acc[8][4];
            #pragma unroll
            for (int tt = 0; tt < 8; tt++)
                #pragma unroll
                for (int r = 0; r < 4; r++) acc[tt][r] = 0.f;

            if (t == 0) { fillF(gcBase); fillF(gcBase + 1); fillF(gcBase + 2); }

            for (int c = 0; c < nc; c++) {
                const int C = gcBase + c, st = C & 3;
                if (t == 0 && c + 3 < nc) fillF(C + 3);
                mbar_wait(mbF + 8 * st, (u32)(C >> 2) & 1u);
                const u32* A = sm + st * 3072;
                const u32* W = A + 1024;
                u32 ah[4], al[4];
                *(uint4*)ah = *(const uint4*)&A[(mt * 2 + 0) * 128 + lane * 4];
                *(uint4*)al = *(const uint4*)&A[(mt * 2 + 1) * 128 + lane * 4];
                #pragma unroll
                for (int tt = 0; tt < 8; tt++) {
                    const int nt = nh * 8 + tt;
                    u32 bh[2], bl[2];
                    *(ull*)bh = *(const ull*)&W[(nt * 2 + 0) * 64 + lane * 2];
                    *(ull*)bl = *(const ull*)&W[(nt * 2 + 1) * 64 + lane * 2];
                    mma16816(acc[tt], ah, bh);
                    mma16816(acc[tt], ah, bl);
                    mma16816(acc[tt], al, bh);
                }
                __syncwarp();
                if (lane == 0) mbar_arrive(mbE + 8 * st);
            }
            gcBase += nc;

            const int m0 = mt * 16;
            #pragma unroll
            for (int tt = 0; tt < 8; tt++) {
                const int nb = nh * 64 + tt * 8 + tig * 2;
                *(float2*)&zbuf[(m0 + gid) * 128 + nb]     = make_float2(acc[tt][0], acc[tt][1]);
                *(float2*)&zbuf[(m0 + gid + 8) * 128 + nb] = make_float2(acc[tt][2], acc[tt][3]);
            }
            __syncthreads();

            u32* himg = &g_hA[prCur][layer][0];
            #pragma unroll
            for (int i = 0; i < 8; i++) {
                const int r = wid * 8 + i;
                const float4 z = *(const float4*)&zbuf[r * 128 + lane * 4];
                const float zi = z.x + b4[0], zf = z.y + b4[1];
                const float zg = z.z + b4[2], zo = z.w + b4[3];
                const float ig = 1.f / (1.f + expf(-zi));
                const float fg = 1.f / (1.f + expf(-zf));
                const float og = 1.f / (1.f + expf(-zo));
                const float cn = fg * creg[i] + ig * tanhf(zg);
                const float hn = og * tanhf(cn);
                creg[i] = cn;
                const int rl = r & 15, mtr = r >> 4;
                const int word = ((rl & 7) * 4 + tigk) * 4 + ((rl >> 3) | (regk << 1));
                const u32 ihi = kchunk * 1024 + (mtr * 2 + 0) * 128 + word;
                const u32 ilo = kchunk * 1024 + (mtr * 2 + 1) * 128 + word;
                const __nv_bfloat16 hh = __float2bfloat16(hn);
                const __nv_bfloat16 hl = __float2bfloat16(hn - __bfloat162float(hh));
                ((__nv_bfloat16*)&himg[ihi])[byk] = hh;
                ((__nv_bfloat16*)&himg[ilo])[byk] = hl;
                if (layer == 3) out[(size_t)s * BH_ + r * 1024 + hcol] = hn;
                if (s == 511) {
                    out[HS_ + (size_t)layer * BH_ + r * 1024 + hcol] = hn;
                    out[HS_ + 262144ull + (size_t)layer * BH_ + r * 1024 + hcol] = cn;
                }
            }
            __syncthreads();
        }
        if (w < 512 + 2) grid_sync();
    }
}

extern "C" void kernel_launch(void* const* d_in, const int* in_sizes, int n_in,
                              void* d_out, int out_size)
{
    const float* x   = (const float*)d_in[0];
    const float* Wx0 = (const float*)d_in[1];
    const float* Wh0 = (const float*)d_in[2];
    const float* b0  = (const float*)d_in[3];
    const float* Wxr = (const float*)d_in[4];
    const float* Whr = (const float*)d_in[5];
    const float* br  = (const float*)d_in[6];
    float* out = (float*)d_out;

    void* hp;
    cudaGetSymbolAddress(&hp, g_hA);
    cudaMemsetAsync(hp, 0, sizeof(u32) * 2 * 4 * 65536, 0);

    prep_w<<<15360, 256>>>(Wx0, Wh0, Wxr, Whr);
    prep_x<<<16384, 256>>>(x);

    cudaFuncSetAttribute(lstm_persist, cudaFuncAttributeMaxDynamicSharedMemorySize, SMEM_DYN);
    lstm_persist<<<NCTA, NTHR, SMEM_DYN>>>(b0, br, out);
}

// round 9
// speedup vs baseline: 3.0008x; 1.5812x over previous
#include <cuda_runtime.h>
#include <cuda_bf16.h>
#include <math.h>
#include <cstdint>

typedef unsigned int u32;
typedef unsigned long long ull;

#define NCTA 128
#define NTHR 288          // 8 compute warps + 1 producer warp
#define HS_  33554432ull
#define BH_  65536
#define SMEM_DYN 131136   // 4 stages x 24KB + 32KB zbuf + barriers

__device__ __align__(16) u32 g_W[31457280];      // weight images, B-fragment order
__device__ __align__(16) u32 g_x[16777216];      // x images, A-fragment order
__device__ __align__(16) u32 g_hA[2][4][65536];  // h images [parity][layer]
__device__ unsigned g_bar_count;
__device__ volatile unsigned g_bar_gen;

__device__ __forceinline__ u32 sm_u32(const void* p) {
    u32 a;
    asm("{.reg .u64 t; cvta.to.shared.u64 t, %1; cvt.u32.u64 %0, t;}" : "=r"(a) : "l"(p));
    return a;
}
__device__ __forceinline__ void bulk_cp(u32 dst, const void* src, u32 bytes, u32 mbar) {
    asm volatile("cp.async.bulk.shared::cluster.global.mbarrier::complete_tx::bytes "
                 "[%0], [%1], %2, [%3];" :: "r"(dst), "l"(src), "r"(bytes), "r"(mbar) : "memory");
}
__device__ __forceinline__ void mbar_init(u32 a, u32 c) {
    asm volatile("mbarrier.init.shared.b64 [%0], %1;" :: "r"(a), "r"(c) : "memory");
}
__device__ __forceinline__ void mbar_expect(u32 a, u32 tx) {
    asm volatile("mbarrier.arrive.expect_tx.shared.b64 _, [%0], %1;" :: "r"(a), "r"(tx) : "memory");
}
__device__ __forceinline__ void mbar_arrive(u32 a) {
    asm volatile("mbarrier.arrive.shared.b64 _, [%0];" :: "r"(a) : "memory");
}
__device__ __forceinline__ void mbar_wait(u32 a, u32 ph) {
    u32 done = 0;
    while (!done)
        asm volatile("{.reg .pred p; mbarrier.try_wait.parity.acquire.cta.shared::cta.b64 "
                     "p, [%1], %2, 0x989680; selp.b32 %0,1,0,p;}"
                     : "=r"(done) : "r"(a), "r"(ph) : "memory");
}
__device__ __forceinline__ void mma16816(float* c, const u32* a, const u32* b) {
    asm("mma.sync.aligned.m16n8k16.row.col.f32.bf16.bf16.f32 "
        "{%0,%1,%2,%3}, {%4,%5,%6,%7}, {%8,%9}, {%0,%1,%2,%3};"
        : "+f"(c[0]), "+f"(c[1]), "+f"(c[2]), "+f"(c[3])
        : "r"(a[0]), "r"(a[1]), "r"(a[2]), "r"(a[3]), "r"(b[0]), "r"(b[1]));
}
__device__ __forceinline__ u32 pack2(float v0, float v1, bool lo) {
    __nv_bfloat16 h0 = __float2bfloat16(v0), h1 = __float2bfloat16(v1);
    if (lo) {
        h0 = __float2bfloat16(v0 - __bfloat162float(h0));
        h1 = __float2bfloat16(v1 - __bfloat162float(h1));
    }
    u32 u0 = ((__nv_bfloat16_raw)h0).x, u1 = ((__nv_bfloat16_raw)h1).x;
    return u0 | (u1 << 16);
}
__device__ __forceinline__ void grid_sync() {
    __syncthreads();
    if (threadIdx.x == 0) {
        __threadfence();
        unsigned gen = g_bar_gen;
        if (atomicAdd(&g_bar_count, 1u) == NCTA - 1u) {
            g_bar_count = 0;
            __threadfence();
            g_bar_gen = gen + 1u;
        } else {
            while (g_bar_gen == gen) __nanosleep(64);
        }
        __threadfence();
    }
    __syncthreads();
}

__global__ void __launch_bounds__(256) prep_x(const float* __restrict__ x)
{
    const int s = blockIdx.x >> 5, c = blockIdx.x & 31;
    const int t = threadIdx.x;
    u32* dst = g_x + (size_t)blockIdx.x * 1024;
    #pragma unroll
    for (int q = 0; q < 4; q++) {
        const int gw = t + 256 * q;
        const int mt = gw >> 8, rem = gw & 255, hl = rem >> 7, w = rem & 127;
        const int lane = w >> 2, reg = w & 3;
        const int row = mt * 16 + (lane >> 2) + (reg & 1) * 8;
        const int k   = c * 16 + (lane & 3) * 2 + (reg >> 1) * 8;
        const float* p = x + (size_t)s * 32768 + row * 512 + k;
        dst[gw] = pack2(p[0], p[1], hl != 0);
    }
}

__global__ void __launch_bounds__(256) prep_w(
    const float* __restrict__ Wx0, const float* __restrict__ Wh0,
    const float* __restrict__ Wxr, const float* __restrict__ Whr)
{
    const int b = blockIdx.x;
    int l, nblk, c;
    if (b < 3072) { l = 0; nblk = b / 96; c = b % 96; }
    else { int r = b - 3072; l = 1 + r / 4096; r %= 4096; nblk = r / 128; c = r % 128; }
    const int ntA = (l == 0) ? 32 : 64;
    const float* Wsrc; int kb;
    if (c < ntA) { Wsrc = (l == 0) ? Wx0 : Wxr + (size_t)(l - 1) * 4194304; kb = c * 16; }
    else         { Wsrc = (l == 0) ? Wh0 : Whr + (size_t)(l - 1) * 4194304; kb = (c - ntA) * 16; }
    u32* dst = g_W + (size_t)b * 2048;
    const int t = threadIdx.x;
    #pragma unroll
    for (int q = 0; q < 8; q++) {
        const int gw = t + 256 * q;
        const int nt = gw >> 7, rem = gw & 127, hl = rem >> 6, w = rem & 63;
        const int lane = w >> 1, reg = w & 1;
        const int n = nt * 8 + (lane >> 2);
        const int zc = (n & 3) * 1024 + nblk * 32 + (n >> 2);
        const int k = kb + (lane & 3) * 2 + reg * 8;
        dst[gw] = pack2(Wsrc[(size_t)k * 4096 + zc], Wsrc[(size_t)(k + 1) * 4096 + zc], hl != 0);
    }
}

__global__ void __launch_bounds__(NTHR, 1)
lstm_persist(const float* __restrict__ b0, const float* __restrict__ br,
             float* __restrict__ out)
{
    extern __shared__ __align__(16) u32 sm[];
    float* zbuf = (float*)(sm + 24576);          // after 96KB of stages
    const u32 smb = sm_u32(sm);
    const u32 mbF = smb + 131072u;               // full[4]
    const u32 mbE = smb + 131104u;               // empty[4]

    const int layer = blockIdx.x >> 5, nblk = blockIdx.x & 31;
    const int t = threadIdx.x, lane = t & 31, wid = t >> 5;
    const int mt = wid & 3, nh = (wid >> 2) & 1;
    const int gid = lane >> 2, tig = lane & 3;
    const int hcol = nblk * 32 + lane;
    const int ntA = (layer == 0) ? 32 : 64;
    const int nc  = ntA + 64;                    // 96 or 128 chunks (even)
    const int np  = nc >> 1;                     // pairs per wave
    const size_t wbase = (layer == 0) ? (size_t)nblk * 96
                                      : 3072 + ((size_t)(layer - 1) * 32 + nblk) * 128;
    const float* bias = (layer == 0) ? b0 : br + (size_t)(layer - 1) * 4096;

    if (t == 0) {
        #pragma unroll
        for (int i = 0; i < 4; i++) { mbar_init(mbF + 8 * i, 1); mbar_init(mbE + 8 * i, 8); }
        asm volatile("fence.proxy.async;" ::: "memory");
    }
    __syncthreads();

    float b4[4];
    #pragma unroll
    for (int g = 0; g < 4; g++) b4[g] = __ldg(bias + g * 1024 + hcol);
    float creg[8];
    #pragma unroll
    for (int i = 0; i < 8; i++) creg[i] = 0.f;

    const int kchunk = hcol >> 4, kl = hcol & 15;
    const int tigk = (kl >> 1) & 3, regk = kl >> 3, byk = kl & 1;

    int gpBase = 0;   // cumulative pair counter

    for (int w = 0; w < 512 + 3; w++) {
        const int s = w - layer;
        if (s >= 0 && s < 512) {
            const int prPrev = (w & 1) ^ 1, prCur = w & 1;

            const u32* a0 = (layer == 0) ? g_x + (size_t)s * 32768
                                         : &g_hA[prPrev][layer - 1][0];
            const u32* a1 = &g_hA[prPrev][layer][0];

            if (wid == 8) {
                // ---- producer warp: issue all pairs with ring backpressure ----
                if (lane == 0) {
                    for (int p = 0; p < np; p++) {
                        const int P = gpBase + p, st = P & 3;
                        if (P >= 4) mbar_wait(mbE + 8 * st, (u32)(((P >> 2) - 1) & 1));
                        const u32 full = mbF + 8 * st;
                        mbar_expect(full, 24576u);
                        #pragma unroll
                        for (int q = 0; q < 2; q++) {
                            const int c = p * 2 + q;
                            const u32* A = (c < ntA) ? a0 + (size_t)c * 1024
                                                     : a1 + (size_t)(c - ntA) * 1024;
                            const u32 d = smb + (u32)st * 24576u + (u32)q * 12288u;
                            bulk_cp(d, A, 4096u, full);
                            bulk_cp(d + 4096u, g_W + (wbase + p * 2 + q) * 2048, 8192u, full);
                        }
                    }
                }
            } else {
                // ---- 8 compute warps ----
                float acc[8][4];
                #pragma unroll
                for (int tt = 0; tt < 8; tt++)
                    #pragma unroll
                    for (int r = 0; r < 4; r++) acc[tt][r] = 0.f;

                for (int p = 0; p < np; p++) {
                    const int P = gpBase + p, st = P & 3;
                    mbar_wait(mbF + 8 * st, (u32)((P >> 2) & 1));
                    #pragma unroll
                    for (int q = 0; q < 2; q++) {
                        const u32* A = sm + st * 6144 + q * 3072;
                        const u32* W = A + 1024;
                        u32 ah[4], al[4];
                        *(uint4*)ah = *(const uint4*)&A[(mt * 2 + 0) * 128 + lane * 4];
                        *(uint4*)al = *(const uint4*)&A[(mt * 2 + 1) * 128 + lane * 4];
                        #pragma unroll
                        for (int tt = 0; tt < 8; tt++) {
                            const int nt = nh * 8 + tt;
                            u32 bh[2], bl[2];
                            *(ull*)bh = *(const ull*)&W[(nt * 2 + 0) * 64 + lane * 2];
                            *(ull*)bl = *(const ull*)&W[(nt * 2 + 1) * 64 + lane * 2];
                            mma16816(acc[tt], ah, bh);
                            mma16816(acc[tt], ah, bl);
                            mma16816(acc[tt], al, bh);
                        }
                    }
                    __syncwarp();
                    if (lane == 0) mbar_arrive(mbE + 8 * st);
                }

                const int m0 = mt * 16;
                #pragma unroll
                for (int tt = 0; tt < 8; tt++) {
                    const int nb = nh * 64 + tt * 8 + tig * 2;
                    *(float2*)&zbuf[(m0 + gid) * 128 + nb]     = make_float2(acc[tt][0], acc[tt][1]);
                    *(float2*)&zbuf[(m0 + gid + 8) * 128 + nb] = make_float2(acc[tt][2], acc[tt][3]);
                }
            }
            gpBase += np;
            __syncthreads();

            if (wid < 8) {
                u32* himg = &g_hA[prCur][layer][0];
                #pragma unroll
                for (int i = 0; i < 8; i++) {
                    const int r = wid * 8 + i;
                    const float4 z = *(const float4*)&zbuf[r * 128 + lane * 4];
                    const float zi = z.x + b4[0], zf = z.y + b4[1];
                    const float zg = z.z + b4[2], zo = z.w + b4[3];
                    const float ig = 1.f / (1.f + expf(-zi));
                    const float fg = 1.f / (1.f + expf(-zf));
                    const float og = 1.f / (1.f + expf(-zo));
                    const float cn = fg * creg[i] + ig * tanhf(zg);
                    const float hn = og * tanhf(cn);
                    creg[i] = cn;
                    const int rl = r & 15, mtr = r >> 4;
                    const int word = ((rl & 7) * 4 + tigk) * 4 + ((rl >> 3) | (regk << 1));
                    const u32 ihi = kchunk * 1024 + (mtr * 2 + 0) * 128 + word;
                    const u32 ilo = kchunk * 1024 + (mtr * 2 + 1) * 128 + word;
                    const __nv_bfloat16 hh = __float2bfloat16(hn);
                    const __nv_bfloat16 hl = __float2bfloat16(hn - __bfloat162float(hh));
                    ((__nv_bfloat16*)&himg[ihi])[byk] = hh;
                    ((__nv_bfloat16*)&himg[ilo])[byk] = hl;
                    if (layer == 3) out[(size_t)s * BH_ + r * 1024 + hcol] = hn;
                    if (s == 511) {
                        out[HS_ + (size_t)layer * BH_ + r * 1024 + hcol] = hn;
                        out[HS_ + 262144ull + (size_t)layer * BH_ + r * 1024 + hcol] = cn;
                    }
                }
            }
        }
        if (w < 512 + 2) grid_sync();
    }
}

extern "C" void kernel_launch(void* const* d_in, const int* in_sizes, int n_in,
                              void* d_out, int out_size)
{
    const float* x   = (const float*)d_in[0];
    const float* Wx0 = (const float*)d_in[1];
    const float* Wh0 = (const float*)d_in[2];
    const float* b0  = (const float*)d_in[3];
    const float* Wxr = (const float*)d_in[4];
    const float* Whr = (const float*)d_in[5];
    const float* br  = (const float*)d_in[6];
    float* out = (float*)d_out;

    void* hp;
    cudaGetSymbolAddress(&hp, g_hA);
    cudaMemsetAsync(hp, 0, sizeof(u32) * 2 * 4 * 65536, 0);

    prep_w<<<15360, 256>>>(Wx0, Wh0, Wxr, Whr);
    prep_x<<<16384, 256>>>(x);

    cudaFuncSetAttribute(lstm_persist, cudaFuncAttributeMaxDynamicSharedMemorySize, SMEM_DYN);
    lstm_persist<<<NCTA, NTHR, SMEM_DYN>>>(b0, br, out);
}

// round 10
// speedup vs baseline: 3.2997x; 1.0996x over previous
#include <cuda_runtime.h>
#include <cuda_bf16.h>
#include <math.h>
#include <cstdint>

typedef unsigned int u32;
typedef unsigned long long ull;

#define NCTA 128
#define NTHR 288          // 8 compute warps + 1 producer warp
#define HS_  33554432ull
#define BH_  65536
#define SMEM_DYN 131136   // 4 stages x 24KB + 32KB zbuf + barriers

__device__ __align__(16) u32 g_W[31457280];      // weight images, B-fragment order
__device__ __align__(16) u32 g_x[16777216];      // x images, A-fragment order
__device__ __align__(16) u32 g_hA[2][4][65536];  // h images [parity][layer]
__device__ unsigned g_bar_count;
__device__ volatile unsigned g_bar_gen;

__device__ __forceinline__ u32 sm_u32(const void* p) {
    u32 a;
    asm("{.reg .u64 t; cvta.to.shared.u64 t, %1; cvt.u32.u64 %0, t;}" : "=r"(a) : "l"(p));
    return a;
}
__device__ __forceinline__ void bulk_cp(u32 dst, const void* src, u32 bytes, u32 mbar) {
    asm volatile("cp.async.bulk.shared::cluster.global.mbarrier::complete_tx::bytes "
                 "[%0], [%1], %2, [%3];" :: "r"(dst), "l"(src), "r"(bytes), "r"(mbar) : "memory");
}
__device__ __forceinline__ void mbar_init(u32 a, u32 c) {
    asm volatile("mbarrier.init.shared.b64 [%0], %1;" :: "r"(a), "r"(c) : "memory");
}
__device__ __forceinline__ void mbar_expect(u32 a, u32 tx) {
    asm volatile("mbarrier.arrive.expect_tx.shared.b64 _, [%0], %1;" :: "r"(a), "r"(tx) : "memory");
}
__device__ __forceinline__ void mbar_arrive(u32 a) {
    asm volatile("mbarrier.arrive.shared.b64 _, [%0];" :: "r"(a) : "memory");
}
__device__ __forceinline__ void mbar_wait(u32 a, u32 ph) {
    u32 done = 0;
    while (!done)
        asm volatile("{.reg .pred p; mbarrier.try_wait.parity.acquire.cta.shared::cta.b64 "
                     "p, [%1], %2, 0x989680; selp.b32 %0,1,0,p;}"
                     : "=r"(done) : "r"(a), "r"(ph) : "memory");
}
__device__ __forceinline__ void mma16816(float* c, const u32* a, const u32* b) {
    asm("mma.sync.aligned.m16n8k16.row.col.f32.bf16.bf16.f32 "
        "{%0,%1,%2,%3}, {%4,%5,%6,%7}, {%8,%9}, {%0,%1,%2,%3};"
        : "+f"(c[0]), "+f"(c[1]), "+f"(c[2]), "+f"(c[3])
        : "r"(a[0]), "r"(a[1]), "r"(a[2]), "r"(a[3]), "r"(b[0]), "r"(b[1]));
}
__device__ __forceinline__ u32 pack2(float v0, float v1, bool lo) {
    __nv_bfloat16 h0 = __float2bfloat16(v0), h1 = __float2bfloat16(v1);
    if (lo) {
        h0 = __float2bfloat16(v0 - __bfloat162float(h0));
        h1 = __float2bfloat16(v1 - __bfloat162float(h1));
    }
    u32 u0 = ((__nv_bfloat16_raw)h0).x, u1 = ((__nv_bfloat16_raw)h1).x;
    return u0 | (u1 << 16);
}
__device__ __forceinline__ float fsig(float x) {
    return __fdividef(1.f, 1.f + __expf(-x));
}
__device__ __forceinline__ float ftanh(float x) {
    const float e = __expf(-2.f * x);
    return __fdividef(1.f - e, 1.f + e);
}
__device__ __forceinline__ void grid_sync() {
    __syncthreads();
    if (threadIdx.x == 0) {
        __threadfence();
        unsigned gen = g_bar_gen;
        if (atomicAdd(&g_bar_count, 1u) == NCTA - 1u) {
            g_bar_count = 0;
            __threadfence();
            g_bar_gen = gen + 1u;
        } else {
            while (g_bar_gen == gen) __nanosleep(64);
        }
        __threadfence();
    }
    __syncthreads();
}

__global__ void __launch_bounds__(256) prep_x(const float* __restrict__ x)
{
    const int s = blockIdx.x >> 5, c = blockIdx.x & 31;
    const int t = threadIdx.x;
    u32* dst = g_x + (size_t)blockIdx.x * 1024;
    #pragma unroll
    for (int q = 0; q < 4; q++) {
        const int gw = t + 256 * q;
        const int mt = gw >> 8, rem = gw & 255, hl = rem >> 7, w = rem & 127;
        const int lane = w >> 2, reg = w & 3;
        const int row = mt * 16 + (lane >> 2) + (reg & 1) * 8;
        const int k   = c * 16 + (lane & 3) * 2 + (reg >> 1) * 8;
        const float* p = x + (size_t)s * 32768 + row * 512 + k;
        dst[gw] = pack2(p[0], p[1], hl != 0);
    }
}

// W image: per chunk [nt 0..15][lane 0..31][slot 0..3], slot = {bh0,bh1,bl0,bl1}
__global__ void __launch_bounds__(256) prep_w(
    const float* __restrict__ Wx0, const float* __restrict__ Wh0,
    const float* __restrict__ Wxr, const float* __restrict__ Whr)
{
    const int b = blockIdx.x;
    int l, nblk, c;
    if (b < 3072) { l = 0; nblk = b / 96; c = b % 96; }
    else { int r = b - 3072; l = 1 + r / 4096; r %= 4096; nblk = r / 128; c = r % 128; }
    const int ntA = (l == 0) ? 32 : 64;
    const float* Wsrc; int kb;
    if (c < ntA) { Wsrc = (l == 0) ? Wx0 : Wxr + (size_t)(l - 1) * 4194304; kb = c * 16; }
    else         { Wsrc = (l == 0) ? Wh0 : Whr + (size_t)(l - 1) * 4194304; kb = (c - ntA) * 16; }
    u32* dst = g_W + (size_t)b * 2048;
    const int t = threadIdx.x;
    #pragma unroll
    for (int q = 0; q < 8; q++) {
        const int gw = t + 256 * q;
        const int nt = gw >> 7, rem = gw & 127, lane = rem >> 2, slot = rem & 3;
        const int hl = slot >> 1, reg = slot & 1;
        const int n = nt * 8 + (lane >> 2);
        const int zc = (n & 3) * 1024 + nblk * 32 + (n >> 2);
        const int k = kb + (lane & 3) * 2 + reg * 8;
        dst[gw] = pack2(Wsrc[(size_t)k * 4096 + zc], Wsrc[(size_t)(k + 1) * 4096 + zc], hl != 0);
    }
}

__global__ void __launch_bounds__(NTHR, 1)
lstm_persist(const float* __restrict__ b0, const float* __restrict__ br,
             float* __restrict__ out)
{
    extern __shared__ __align__(16) u32 sm[];
    float* zbuf = (float*)(sm + 24576);
    const u32 smb = sm_u32(sm);
    const u32 mbF = smb + 131072u;
    const u32 mbE = smb + 131104u;

    const int layer = blockIdx.x >> 5, nblk = blockIdx.x & 31;
    const int t = threadIdx.x, lane = t & 31, wid = t >> 5;
    const int mp = wid & 1, nq = wid >> 1;      // warp tile: 2 m-tiles x 4 n-tiles
    const int gid = lane >> 2, tig = lane & 3;
    const int hcol = nblk * 32 + lane;
    const int ntA = (layer == 0) ? 32 : 64;
    const int nc  = ntA + 64;
    const int np  = nc >> 1;
    const size_t wbase = (layer == 0) ? (size_t)nblk * 96
                                      : 3072 + ((size_t)(layer - 1) * 32 + nblk) * 128;
    const float* bias = (layer == 0) ? b0 : br + (size_t)(layer - 1) * 4096;

    if (t == 0) {
        #pragma unroll
        for (int i = 0; i < 4; i++) { mbar_init(mbF + 8 * i, 1); mbar_init(mbE + 8 * i, 8); }
        asm volatile("fence.proxy.async;" ::: "memory");
    }
    __syncthreads();

    float b4[4];
    #pragma unroll
    for (int g = 0; g < 4; g++) b4[g] = __ldg(bias + g * 1024 + hcol);
    float creg[8];
    #pragma unroll
    for (int i = 0; i < 8; i++) creg[i] = 0.f;

    const int kchunk = hcol >> 4, kl = hcol & 15;
    const int tigk = (kl >> 1) & 3, regk = kl >> 3, byk = kl & 1;

    int gpBase = 0;

    for (int w = 0; w < 512 + 3; w++) {
        const int s = w - layer;
        if (s >= 0 && s < 512) {
            const int prPrev = (w & 1) ^ 1, prCur = w & 1;

            const u32* a0 = (layer == 0) ? g_x + (size_t)s * 32768
                                         : &g_hA[prPrev][layer - 1][0];
            const u32* a1 = &g_hA[prPrev][layer][0];

            if (wid == 8) {
                if (lane == 0) {
                    for (int p = 0; p < np; p++) {
                        const int P = gpBase + p, st = P & 3;
                        if (P >= 4) mbar_wait(mbE + 8 * st, (u32)(((P >> 2) - 1) & 1));
                        const u32 full = mbF + 8 * st;
                        mbar_expect(full, 24576u);
                        #pragma unroll
                        for (int q = 0; q < 2; q++) {
                            const int c = p * 2 + q;
                            const u32* A = (c < ntA) ? a0 + (size_t)c * 1024
                                                     : a1 + (size_t)(c - ntA) * 1024;
                            const u32 d = smb + (u32)st * 24576u + (u32)q * 12288u;
                            bulk_cp(d, A, 4096u, full);
                            bulk_cp(d + 4096u, g_W + (wbase + p * 2 + q) * 2048, 8192u, full);
                        }
                    }
                }
            } else {
                float acc[2][4][4];
                #pragma unroll
                for (int m = 0; m < 2; m++)
                    #pragma unroll
                    for (int tt = 0; tt < 4; tt++)
                        #pragma unroll
                        for (int r = 0; r < 4; r++) acc[m][tt][r] = 0.f;

                for (int p = 0; p < np; p++) {
                    const int P = gpBase + p, st = P & 3;
                    mbar_wait(mbF + 8 * st, (u32)((P >> 2) & 1));
                    #pragma unroll
                    for (int q = 0; q < 2; q++) {
                        const u32* A = sm + st * 6144 + q * 3072;
                        const u32* W = A + 1024;
                        u32 ah[2][4], al[2][4];
                        #pragma unroll
                        for (int m = 0; m < 2; m++) {
                            const int mt = mp * 2 + m;
                            *(uint4*)ah[m] = *(const uint4*)&A[(mt * 2 + 0) * 128 + lane * 4];
                            *(uint4*)al[m] = *(const uint4*)&A[(mt * 2 + 1) * 128 + lane * 4];
                        }
                        #pragma unroll
                        for (int tt = 0; tt < 4; tt++) {
                            const int nt = nq * 4 + tt;
                            const uint4 bv = *(const uint4*)&W[nt * 128 + lane * 4];
                            u32 bh[2] = { bv.x, bv.y }, bl[2] = { bv.z, bv.w };
                            #pragma unroll
                            for (int m = 0; m < 2; m++) {
                                mma16816(acc[m][tt], ah[m], bh);
                                mma16816(acc[m][tt], ah[m], bl);
                                mma16816(acc[m][tt], al[m], bh);
                            }
                        }
                    }
                    __syncwarp();
                    if (lane == 0) mbar_arrive(mbE + 8 * st);
                }

                #pragma unroll
                for (int m = 0; m < 2; m++) {
                    const int m0 = (mp * 2 + m) * 16;
                    #pragma unroll
                    for (int tt = 0; tt < 4; tt++) {
                        const int nb = (nq * 4 + tt) * 8 + tig * 2;
                        *(float2*)&zbuf[(m0 + gid) * 128 + nb] =
                            make_float2(acc[m][tt][0], acc[m][tt][1]);
                        *(float2*)&zbuf[(m0 + gid + 8) * 128 + nb] =
                            make_float2(acc[m][tt][2], acc[m][tt][3]);
                    }
                }
            }
            gpBase += np;
            __syncthreads();

            if (wid < 8) {
                u32* himg = &g_hA[prCur][layer][0];
                #pragma unroll
                for (int i = 0; i < 8; i++) {
                    const int r = wid * 8 + i;
                    const float4 z = *(const float4*)&zbuf[r * 128 + lane * 4];
                    const float ig = fsig(z.x + b4[0]);
                    const float fg = fsig(z.y + b4[1]);
                    const float og = fsig(z.w + b4[3]);
                    const float cn = fg * creg[i] + ig * ftanh(z.z + b4[2]);
                    const float hn = og * ftanh(cn);
                    creg[i] = cn;
                    const int rl = r & 15, mtr = r >> 4;
                    const int word = ((rl & 7) * 4 + tigk) * 4 + ((rl >> 3) | (regk << 1));
                    const u32 ihi = kchunk * 1024 + (mtr * 2 + 0) * 128 + word;
                    const u32 ilo = kchunk * 1024 + (mtr * 2 + 1) * 128 + word;
                    const __nv_bfloat16 hh = __float2bfloat16(hn);
                    const __nv_bfloat16 hl = __float2bfloat16(hn - __bfloat162float(hh));
                    ((__nv_bfloat16*)&himg[ihi])[byk] = hh;
                    ((__nv_bfloat16*)&himg[ilo])[byk] = hl;
                    if (layer == 3) out[(size_t)s * BH_ + r * 1024 + hcol] = hn;
                    if (s == 511) {
                        out[HS_ + (size_t)layer * BH_ + r * 1024 + hcol] = hn;
                        out[HS_ + 262144ull + (size_t)layer * BH_ + r * 1024 + hcol] = cn;
                    }
                }
            }
        }
        if (w < 512 + 2) grid_sync();
    }
}

extern "C" void kernel_launch(void* const* d_in, const int* in_sizes, int n_in,
                              void* d_out, int out_size)
{
    const float* x   = (const float*)d_in[0];
    const float* Wx0 = (const float*)d_in[1];
    const float* Wh0 = (const float*)d_in[2];
    const float* b0  = (const float*)d_in[3];
    const float* Wxr = (const float*)d_in[4];
    const float* Whr = (const float*)d_in[5];
    const float* br  = (const float*)d_in[6];
    float* out = (float*)d_out;

    void* hp;
    cudaGetSymbolAddress(&hp, g_hA);
    cudaMemsetAsync(hp, 0, sizeof(u32) * 2 * 4 * 65536, 0);

    prep_w<<<15360, 256>>>(Wx0, Wh0, Wxr, Whr);
    prep_x<<<16384, 256>>>(x);

    cudaFuncSetAttribute(lstm_persist, cudaFuncAttributeMaxDynamicSharedMemorySize, SMEM_DYN);
    lstm_persist<<<NCTA, NTHR, SMEM_DYN>>>(b0, br, out);
}